// round 7
// baseline (speedup 1.0000x reference)
#include <cuda_runtime.h>

// Problem constants (B=1, H=32, Q=1024, S=4096, D=128)
#define SEQ      4096
#define ROWS     32768      // B*H*Q rows of attn_weights
#define START    4
#define HEAVY    409        // int(4096*0.1)
#define RSTART   3687       // 4096 - min(409,512)
#define NCAND    3683       // RSTART - START
#define NKEEP    822        // 4 + 409 + 409
#define HEADS    32
#define NBLK     148        // one exact wave, all co-resident
#define NTHR     1024
#define ICH      25         // candidates per block in rank phase (148*25>=3683)
#define NFIX     413        // START + recent rows (selection-independent)
#define TOTAL_F  (2*HEADS*NFIX*32)    // fixed-gather float4 count  = 845824
#define TOTAL_H  (2*HEADS*HEAVY*32)   // heavy-gather float4 count  = 837632

// Scratch. g_sums is atomically accumulated so it MUST be zero at entry:
// the tail kernel's last block re-zeroes it (all consumers done by then).
__device__ double g_sums[SEQ];
__device__ int    g_rank[NCAND];
__device__ int    g_cnt;      // tail grid barrier
__device__ int    g_done;     // tail epilogue counter

// ================= Kernel 1: column sums (512 MB PURE READ stream) =========
// 148 blocks, contiguous row range each (measured 81.6us @ 83.6% DRAM).
// Thread t owns columns [4t,4t+4) via float4; 8 front-batched LDG.128
// (MLP=8); __ldcs (no reuse). fp32 over 32 rows flushed into fp64 keeps the
// mean accurate to ~1e-8 rel (top-k boundary gap ~1e-5); fp64 atomicAdd
// ordering noise ~1e-13 — selection identical to reference (rel_err 0.0).
__global__ void __launch_bounds__(NTHR, 1) k_colsum(const float* __restrict__ w) {
    const int t = threadIdx.x;
    const int b = blockIdx.x;
    const int r0 = (int)((long long)ROWS * b / NBLK);
    const int r1 = (int)((long long)ROWS * (b + 1) / NBLK);
    const float4* __restrict__ w4 = (const float4*)w + t;
    double a0 = 0, a1 = 0, a2 = 0, a3 = 0;
    float  c0 = 0, c1 = 0, c2 = 0, c3 = 0;
    int row = r0, grp = 0;
    for (; row + 8 <= r1; row += 8) {
        float4 v[8];
        #pragma unroll
        for (int k = 0; k < 8; k++)
            v[k] = __ldcs(&w4[(size_t)(row + k) * 1024]);
        float s0x = (v[0].x + v[1].x) + (v[2].x + v[3].x);
        float s1x = (v[4].x + v[5].x) + (v[6].x + v[7].x);
        float s0y = (v[0].y + v[1].y) + (v[2].y + v[3].y);
        float s1y = (v[4].y + v[5].y) + (v[6].y + v[7].y);
        float s0z = (v[0].z + v[1].z) + (v[2].z + v[3].z);
        float s1z = (v[4].z + v[5].z) + (v[6].z + v[7].z);
        float s0w = (v[0].w + v[1].w) + (v[2].w + v[3].w);
        float s1w = (v[4].w + v[5].w) + (v[6].w + v[7].w);
        c0 += s0x + s1x;  c1 += s0y + s1y;
        c2 += s0z + s1z;  c3 += s0w + s1w;
        if (++grp == 4) {                 // flush every 32 rows
            a0 += c0; a1 += c1; a2 += c2; a3 += c3;
            c0 = c1 = c2 = c3 = 0.f; grp = 0;
        }
    }
    for (; row < r1; row++) {
        float4 v = __ldcs(&w4[(size_t)row * 1024]);
        c0 += v.x; c1 += v.y; c2 += v.z; c3 += v.w;
    }
    a0 += c0; a1 += c1; a2 += c2; a3 += c3;
    int s = 4 * t;
    atomicAdd(&g_sums[s + 0], a0);
    atomicAdd(&g_sums[s + 1], a1);
    atomicAdd(&g_sums[s + 2], a2);
    atomicAdd(&g_sums[s + 3], a3);
}

// ===== Kernel 2: rank -> fixed gather -> barrier -> build -> heavy gather ==
__global__ void __launch_bounds__(NTHR, 1)
k_tail(const float4* __restrict__ keys,
       const float4* __restrict__ vals,
       float4* __restrict__ out) {
    __shared__ unsigned long long sj[NCAND];   // all candidate sums
    __shared__ int s_keep[HEAVY];              // heavy source indices (sorted)
    __shared__ int warpsum[32];

    const int t = threadIdx.x;
    const int b = blockIdx.x;
    const int lane = t & 31, w = t >> 5;

    // ---- Phase B: rank via pairwise count (no atomics) --------------------
    // Positive doubles -> u64 bit order isomorphic. Tie-break (equal value,
    // lower index wins) matches jax.lax.top_k. Block owns 25 candidates,
    // one warp per candidate; count loop unrolled x4 (4 independent LDS.64).
    for (int k = t; k < NCAND; k += NTHR)
        sj[k] = __double_as_longlong(__ldcg(&g_sums[START + k]));
    __syncthreads();
    if (w < ICH) {
        int i = b * ICH + w;
        if (i < NCAND) {
            unsigned long long vi = sj[i];
            int cnt = 0;
            int j = lane;
            for (; j + 96 < NCAND; j += 128) {
                unsigned long long v0 = sj[j];
                unsigned long long v1 = sj[j + 32];
                unsigned long long v2 = sj[j + 64];
                unsigned long long v3 = sj[j + 96];
                cnt += (v0 > vi || (v0 == vi && j       < i));
                cnt += (v1 > vi || (v1 == vi && j + 32  < i));
                cnt += (v2 > vi || (v2 == vi && j + 64  < i));
                cnt += (v3 > vi || (v3 == vi && j + 96  < i));
            }
            for (; j < NCAND; j += 32) {
                unsigned long long vj = sj[j];
                cnt += (vj > vi || (vj == vi && j < i));
            }
            #pragma unroll
            for (int o = 16; o; o >>= 1)
                cnt += __shfl_down_sync(0xFFFFFFFFu, cnt, o);
            if (lane == 0) g_rank[i] = cnt;
        }
    }

    // ---- Phase A': fixed gather (sinks + recent) BEFORE the barrier -------
    // Selection-independent 27 MB; absorbs rank latency + barrier skew.
    for (int v = b * NTHR + t; v < TOTAL_F; v += NBLK * NTHR) {
        int d4  = v & 31;
        int row = v >> 5;
        int tensor = row / (HEADS * NFIX);
        int rem = row - tensor * (HEADS * NFIX);
        int h   = rem / NFIX;
        int p   = rem - h * NFIX;                 // 0..412
        int r   = (p < START) ? p : p + HEAVY;    // output row (keep order)
        int s   = (p < START) ? p : (RSTART + p - START);
        const float4* __restrict__ src = tensor ? vals : keys;
        out[(((size_t)(tensor * HEADS + h) * NKEEP + r) << 5) + d4] =
            __ldcs(&src[(((size_t)h * SEQ + s) << 5) + d4]);
    }

    // ---- grid barrier (all 148 blocks co-resident) ------------------------
    __syncthreads();
    if (t == 0) {
        __threadfence();
        atomicAdd(&g_cnt, 1);
        while (*(volatile int*)&g_cnt < NBLK) { }
        __threadfence();
    }
    __syncthreads();

    // ---- Phase C: build heavy keep list (redundant per block) -------------
    // heavy indices sorted ascending; all in (START, RSTART).
    {
        int base = 4 * t;
        int rk[4];
        #pragma unroll
        for (int k = 0; k < 4; k++) {
            int c = base + k;
            rk[k] = (c < NCAND) ? __ldcg(&g_rank[c]) : HEAVY;
        }
        int f[4], loc = 0;
        #pragma unroll
        for (int k = 0; k < 4; k++) {
            f[k] = (rk[k] < HEAVY) ? 1 : 0;
            loc += f[k];
        }
        int v = loc;
        #pragma unroll
        for (int o = 1; o < 32; o <<= 1) {
            int n = __shfl_up_sync(0xFFFFFFFFu, v, o);
            if (lane >= o) v += n;
        }
        if (lane == 31) warpsum[w] = v;
        __syncthreads();
        if (w == 0) {
            int s = warpsum[lane];
            #pragma unroll
            for (int o = 1; o < 32; o <<= 1) {
                int n = __shfl_up_sync(0xFFFFFFFFu, s, o);
                if (lane >= o) s += n;
            }
            warpsum[lane] = s;
        }
        __syncthreads();
        int pos = v - loc + (w > 0 ? warpsum[w - 1] : 0);
        #pragma unroll
        for (int k = 0; k < 4; k++) {
            if (f[k]) { s_keep[pos] = START + base + k; pos++; }
        }
    }
    __syncthreads();

    // ---- Phase D: heavy-row gather (27 MB), unroll handled by hardware ----
    for (int v = b * NTHR + t; v < TOTAL_H; v += NBLK * NTHR) {
        int d4  = v & 31;
        int row = v >> 5;
        int tensor = row / (HEADS * HEAVY);
        int rem = row - tensor * (HEADS * HEAVY);
        int h   = rem / HEAVY;
        int q   = rem - h * HEAVY;                // heavy slot 0..408
        int s   = s_keep[q];
        const float4* __restrict__ src = tensor ? vals : keys;
        out[(((size_t)(tensor * HEADS + h) * NKEEP + (START + q)) << 5) + d4] =
            __ldcs(&src[(((size_t)h * SEQ + s) << 5) + d4]);
    }

    // ---- epilogue: last block resets scratch for the next call ------------
    __syncthreads();
    __shared__ int s_last;
    if (t == 0) {
        __threadfence();
        s_last = (atomicAdd(&g_done, 1) == NBLK - 1) ? 1 : 0;
    }
    __syncthreads();
    if (s_last) {
        for (int i = t; i < SEQ; i += NTHR) g_sums[i] = 0.0;
        if (t == 0) { g_cnt = 0; g_done = 0; }
    }
}

extern "C" void kernel_launch(void* const* d_in, const int* in_sizes, int n_in,
                              void* d_out, int out_size) {
    const float* keys = (const float*)d_in[0];   // (1,32,4096,128)
    const float* vals = (const float*)d_in[1];   // (1,32,4096,128)
    const float* attn = (const float*)d_in[2];   // (1,32,1024,4096)
    float* out = (float*)d_out;                  // 2*32*822*128 f32

    k_colsum<<<NBLK, NTHR>>>(attn);
    k_tail<<<NBLK, NTHR>>>((const float4*)keys, (const float4*)vals,
                           (float4*)out);
}

// round 8
// speedup vs baseline: 1.0103x; 1.0103x over previous
#include <cuda_runtime.h>

// Problem constants (B=1, H=32, Q=1024, S=4096, D=128)
#define SEQ      4096
#define ROWS     32768      // B*H*Q rows of attn_weights
#define START    4
#define HEAVY    409        // int(4096*0.1)
#define RSTART   3687       // 4096 - min(409,512)
#define NCAND    3683       // RSTART - START
#define NKEEP    822        // 4 + 409 + 409
#define HEADS    32
#define NBLK     148        // one exact wave, all co-resident
#define NTHR     1024
#define ICH      25         // candidates per block in rank phase (148*25>=3683)
#define TOTAL_G  (2*HEADS*NKEEP*32)   // full gather float4 count = 1,683,456

// Scratch. g_sums is atomically accumulated so it MUST be zero at entry:
// the tail kernel's last block re-zeroes it (all consumers done by then).
__device__ double g_sums[SEQ];
__device__ int    g_rank[NCAND];
__device__ int    g_cnt;      // tail grid barrier
__device__ int    g_done;     // tail epilogue counter

// ================= Kernel 1: column sums (512 MB PURE READ stream) =========
// 148 blocks, contiguous row range each (measured 81.6us @ 83.6% DRAM).
// Thread t owns columns [4t,4t+4) via float4; 8 front-batched LDG.128
// (MLP=8); __ldcs (no reuse). fp32 over 32 rows flushed into fp64 keeps the
// mean accurate to ~1e-8 rel (top-k boundary gap ~1e-5); fp64 atomicAdd
// ordering noise ~1e-13 — selection identical to reference (rel_err 0.0).
__global__ void __launch_bounds__(NTHR, 1) k_colsum(const float* __restrict__ w) {
    const int t = threadIdx.x;
    const int b = blockIdx.x;
    const int r0 = (int)((long long)ROWS * b / NBLK);
    const int r1 = (int)((long long)ROWS * (b + 1) / NBLK);
    const float4* __restrict__ w4 = (const float4*)w + t;
    double a0 = 0, a1 = 0, a2 = 0, a3 = 0;
    float  c0 = 0, c1 = 0, c2 = 0, c3 = 0;
    int row = r0, grp = 0;
    for (; row + 8 <= r1; row += 8) {
        float4 v[8];
        #pragma unroll
        for (int k = 0; k < 8; k++)
            v[k] = __ldcs(&w4[(size_t)(row + k) * 1024]);
        float s0x = (v[0].x + v[1].x) + (v[2].x + v[3].x);
        float s1x = (v[4].x + v[5].x) + (v[6].x + v[7].x);
        float s0y = (v[0].y + v[1].y) + (v[2].y + v[3].y);
        float s1y = (v[4].y + v[5].y) + (v[6].y + v[7].y);
        float s0z = (v[0].z + v[1].z) + (v[2].z + v[3].z);
        float s1z = (v[4].z + v[5].z) + (v[6].z + v[7].z);
        float s0w = (v[0].w + v[1].w) + (v[2].w + v[3].w);
        float s1w = (v[4].w + v[5].w) + (v[6].w + v[7].w);
        c0 += s0x + s1x;  c1 += s0y + s1y;
        c2 += s0z + s1z;  c3 += s0w + s1w;
        if (++grp == 4) {                 // flush every 32 rows
            a0 += c0; a1 += c1; a2 += c2; a3 += c3;
            c0 = c1 = c2 = c3 = 0.f; grp = 0;
        }
    }
    for (; row < r1; row++) {
        float4 v = __ldcs(&w4[(size_t)row * 1024]);
        c0 += v.x; c1 += v.y; c2 += v.z; c3 += v.w;
    }
    a0 += c0; a1 += c1; a2 += c2; a3 += c3;
    int s = 4 * t;
    atomicAdd(&g_sums[s + 0], a0);
    atomicAdd(&g_sums[s + 1], a1);
    atomicAdd(&g_sums[s + 2], a2);
    atomicAdd(&g_sums[s + 3], a3);
}

// ================= Kernel 2: rank -> barrier -> build -> gather ============
__global__ void __launch_bounds__(NTHR, 1)
k_tail(const float4* __restrict__ keys,
       const float4* __restrict__ vals,
       float4* __restrict__ out) {
    __shared__ unsigned long long sj[NCAND];   // all candidate sums
    __shared__ int s_keep[NKEEP];              // full sorted keep list
    __shared__ int warpsum[32];

    const int t = threadIdx.x;
    const int b = blockIdx.x;
    const int lane = t & 31, w = t >> 5;

    // ---- Phase B: rank via pairwise count (no atomics) --------------------
    // Positive doubles -> u64 bit order isomorphic. Tie-break (equal value,
    // lower index wins) matches jax.lax.top_k. Block owns 25 candidates,
    // one warp per candidate; count loop unrolled x4.
    for (int k = t; k < NCAND; k += NTHR)
        sj[k] = __double_as_longlong(__ldcg(&g_sums[START + k]));
    __syncthreads();
    if (w < ICH) {
        int i = b * ICH + w;
        if (i < NCAND) {
            unsigned long long vi = sj[i];
            int cnt = 0;
            int j = lane;
            for (; j + 96 < NCAND; j += 128) {
                unsigned long long v0 = sj[j];
                unsigned long long v1 = sj[j + 32];
                unsigned long long v2 = sj[j + 64];
                unsigned long long v3 = sj[j + 96];
                cnt += (v0 > vi || (v0 == vi && j       < i));
                cnt += (v1 > vi || (v1 == vi && j + 32  < i));
                cnt += (v2 > vi || (v2 == vi && j + 64  < i));
                cnt += (v3 > vi || (v3 == vi && j + 96  < i));
            }
            for (; j < NCAND; j += 32) {
                unsigned long long vj = sj[j];
                cnt += (vj > vi || (vj == vi && j < i));
            }
            #pragma unroll
            for (int o = 16; o; o >>= 1)
                cnt += __shfl_down_sync(0xFFFFFFFFu, cnt, o);
            if (lane == 0) g_rank[i] = cnt;
        }
    }

    // ---- grid barrier (all 148 blocks co-resident) ------------------------
    __syncthreads();
    if (t == 0) {
        __threadfence();
        atomicAdd(&g_cnt, 1);
        while (*(volatile int*)&g_cnt < NBLK) { }
        __threadfence();
    }
    __syncthreads();

    // ---- Phase C: build full sorted keep list (redundant per block) -------
    // keep = [0..3] ++ heavy(sorted asc, all in (4,3687)) ++ [3687..4095]
    {
        int base = 4 * t;
        int rk[4];
        #pragma unroll
        for (int k = 0; k < 4; k++) {
            int c = base + k;
            rk[k] = (c < NCAND) ? __ldcg(&g_rank[c]) : HEAVY;
        }
        int f[4], loc = 0;
        #pragma unroll
        for (int k = 0; k < 4; k++) {
            f[k] = (rk[k] < HEAVY) ? 1 : 0;
            loc += f[k];
        }
        int v = loc;
        #pragma unroll
        for (int o = 1; o < 32; o <<= 1) {
            int n = __shfl_up_sync(0xFFFFFFFFu, v, o);
            if (lane >= o) v += n;
        }
        if (lane == 31) warpsum[w] = v;
        __syncthreads();
        if (w == 0) {
            int s = warpsum[lane];
            #pragma unroll
            for (int o = 1; o < 32; o <<= 1) {
                int n = __shfl_up_sync(0xFFFFFFFFu, s, o);
                if (lane >= o) s += n;
            }
            warpsum[lane] = s;
        }
        __syncthreads();
        int pos = START + v - loc + (w > 0 ? warpsum[w - 1] : 0);
        #pragma unroll
        for (int k = 0; k < 4; k++) {
            if (f[k]) { s_keep[pos] = START + base + k; pos++; }
        }
        if (t < START) s_keep[t] = t;
        if (t < SEQ - RSTART) s_keep[START + HEAVY + t] = RSTART + t;
    }
    __syncthreads();

    // ---- Phase D: full gather (54 MB), depth-8 pipelined ------------------
    // Three waves per group: 8 LDS (keep idx) -> 8 LDG.128 -> 8 STG.128.
    // MLP=8 per thread (~4KB/warp in flight) to cover DRAM latency.
    {
        const int stride = NBLK * NTHR;         // 151552
        int v = b * NTHR + t;
        for (; v + 7 * stride < TOTAL_G; v += 8 * stride) {
            const float4* srcp[8];
            #pragma unroll
            for (int k = 0; k < 8; k++) {
                int vv  = v + k * stride;
                int d4  = vv & 31;
                int row = vv >> 5;
                int tensor = row / (HEADS * NKEEP);
                int rem = row - tensor * (HEADS * NKEEP);
                int h   = rem / NKEEP;
                int r   = rem - h * NKEEP;
                int s   = s_keep[r];
                const float4* __restrict__ src = tensor ? vals : keys;
                srcp[k] = &src[(((size_t)h * SEQ + s) << 5) + d4];
            }
            float4 d[8];
            #pragma unroll
            for (int k = 0; k < 8; k++) d[k] = __ldcs(srcp[k]);
            #pragma unroll
            for (int k = 0; k < 8; k++) out[v + k * stride] = d[k];
        }
        for (; v < TOTAL_G; v += stride) {
            int d4  = v & 31;
            int row = v >> 5;
            int tensor = row / (HEADS * NKEEP);
            int rem = row - tensor * (HEADS * NKEEP);
            int h   = rem / NKEEP;
            int r   = rem - h * NKEEP;
            int s   = s_keep[r];
            const float4* __restrict__ src = tensor ? vals : keys;
            out[v] = __ldcs(&src[(((size_t)h * SEQ + s) << 5) + d4]);
        }
    }

    // ---- epilogue: last block resets scratch for the next call ------------
    __syncthreads();
    __shared__ int s_last;
    if (t == 0) {
        __threadfence();
        s_last = (atomicAdd(&g_done, 1) == NBLK - 1) ? 1 : 0;
    }
    __syncthreads();
    if (s_last) {
        for (int i = t; i < SEQ; i += NTHR) g_sums[i] = 0.0;
        if (t == 0) { g_cnt = 0; g_done = 0; }
    }
}

extern "C" void kernel_launch(void* const* d_in, const int* in_sizes, int n_in,
                              void* d_out, int out_size) {
    const float* keys = (const float*)d_in[0];   // (1,32,4096,128)
    const float* vals = (const float*)d_in[1];   // (1,32,4096,128)
    const float* attn = (const float*)d_in[2];   // (1,32,1024,4096)
    float* out = (float*)d_out;                  // 2*32*822*128 f32

    k_colsum<<<NBLK, NTHR>>>(attn);
    k_tail<<<NBLK, NTHR>>>((const float4*)keys, (const float4*)vals,
                           (float4*)out);
}

// round 9
// speedup vs baseline: 1.0195x; 1.0091x over previous
#include <cuda_runtime.h>

// Problem constants (B=1, H=32, Q=1024, S=4096, D=128)
#define SEQ      4096
#define ROWS     32768      // B*H*Q rows of attn_weights
#define START    4
#define HEAVY    409        // int(4096*0.1)
#define RSTART   3687       // 4096 - min(409,512)
#define NCAND    3683       // RSTART - START
#define NKEEP    822        // 4 + 409 + 409
#define HEADS    32
#define NBLK     148        // colsum/rank grid: one exact wave
#define NTHR     1024
#define ICH      25         // candidates per block in rank phase (148*25>=3683)
#define TOTAL_G  (2*HEADS*NKEEP*32)   // full gather float4 count = 1,683,456
#define GBLK     296        // gather grid (2 blocks/SM)
#define GTHR     512

// Scratch. g_sums is atomically accumulated so it MUST be zero at entry:
// k_gath re-zeroes it (all consumers finished in the prior kernel).
// g_rank/g_keep are write-before-read each call; g_done reset by its user.
__device__ double g_sums[SEQ];
__device__ int    g_rank[NCAND];
__device__ int    g_keep[NKEEP];
__device__ int    g_done;

// ================= Kernel 1: column sums (512 MB PURE READ stream) =========
// 148 blocks, contiguous row range each (measured 81.6us @ 83.6% DRAM).
// Thread t owns columns [4t,4t+4) via float4; 8 front-batched LDG.128
// (MLP=8); __ldcs (no reuse). fp32 over 32 rows flushed into fp64 keeps the
// mean accurate to ~1e-8 rel (top-k boundary gap ~1e-5); fp64 atomicAdd
// ordering noise ~1e-13 — selection identical to reference (rel_err 0.0).
__global__ void __launch_bounds__(NTHR, 1) k_colsum(const float* __restrict__ w) {
    const int t = threadIdx.x;
    const int b = blockIdx.x;
    const int r0 = (int)((long long)ROWS * b / NBLK);
    const int r1 = (int)((long long)ROWS * (b + 1) / NBLK);
    const float4* __restrict__ w4 = (const float4*)w + t;
    double a0 = 0, a1 = 0, a2 = 0, a3 = 0;
    float  c0 = 0, c1 = 0, c2 = 0, c3 = 0;
    int row = r0, grp = 0;
    for (; row + 8 <= r1; row += 8) {
        float4 v[8];
        #pragma unroll
        for (int k = 0; k < 8; k++)
            v[k] = __ldcs(&w4[(size_t)(row + k) * 1024]);
        float s0x = (v[0].x + v[1].x) + (v[2].x + v[3].x);
        float s1x = (v[4].x + v[5].x) + (v[6].x + v[7].x);
        float s0y = (v[0].y + v[1].y) + (v[2].y + v[3].y);
        float s1y = (v[4].y + v[5].y) + (v[6].y + v[7].y);
        float s0z = (v[0].z + v[1].z) + (v[2].z + v[3].z);
        float s1z = (v[4].z + v[5].z) + (v[6].z + v[7].z);
        float s0w = (v[0].w + v[1].w) + (v[2].w + v[3].w);
        float s1w = (v[4].w + v[5].w) + (v[6].w + v[7].w);
        c0 += s0x + s1x;  c1 += s0y + s1y;
        c2 += s0z + s1z;  c3 += s0w + s1w;
        if (++grp == 4) {                 // flush every 32 rows
            a0 += c0; a1 += c1; a2 += c2; a3 += c3;
            c0 = c1 = c2 = c3 = 0.f; grp = 0;
        }
    }
    for (; row < r1; row++) {
        float4 v = __ldcs(&w4[(size_t)row * 1024]);
        c0 += v.x; c1 += v.y; c2 += v.z; c3 += v.w;
    }
    a0 += c0; a1 += c1; a2 += c2; a3 += c3;
    int s = 4 * t;
    atomicAdd(&g_sums[s + 0], a0);
    atomicAdd(&g_sums[s + 1], a1);
    atomicAdd(&g_sums[s + 2], a2);
    atomicAdd(&g_sums[s + 3], a3);
}

// ================= Kernel 2: rank; last block builds keep list =============
// Positive doubles -> u64 bit order isomorphic. Tie-break (equal value,
// lower index wins) matches jax.lax.top_k. Block owns 25 candidates, one
// warp per candidate, count loop unrolled x4, no atomics in the hot path.
__global__ void __launch_bounds__(NTHR, 1) k_rank() {
    __shared__ unsigned long long sj[NCAND];
    __shared__ int warpsum[32];
    __shared__ int s_last;

    const int t = threadIdx.x;
    const int b = blockIdx.x;
    const int lane = t & 31, w = t >> 5;

    for (int k = t; k < NCAND; k += NTHR)
        sj[k] = __double_as_longlong(__ldcg(&g_sums[START + k]));
    __syncthreads();
    if (w < ICH) {
        int i = b * ICH + w;
        if (i < NCAND) {
            unsigned long long vi = sj[i];
            int cnt = 0;
            int j = lane;
            for (; j + 96 < NCAND; j += 128) {
                unsigned long long v0 = sj[j];
                unsigned long long v1 = sj[j + 32];
                unsigned long long v2 = sj[j + 64];
                unsigned long long v3 = sj[j + 96];
                cnt += (v0 > vi || (v0 == vi && j       < i));
                cnt += (v1 > vi || (v1 == vi && j + 32  < i));
                cnt += (v2 > vi || (v2 == vi && j + 64  < i));
                cnt += (v3 > vi || (v3 == vi && j + 96  < i));
            }
            for (; j < NCAND; j += 32) {
                unsigned long long vj = sj[j];
                cnt += (vj > vi || (vj == vi && j < i));
            }
            #pragma unroll
            for (int o = 16; o; o >>= 1)
                cnt += __shfl_down_sync(0xFFFFFFFFu, cnt, o);
            if (lane == 0) g_rank[i] = cnt;
        }
    }

    // ---- last-arriving block builds the sorted keep list ------------------
    __syncthreads();
    if (t == 0) {
        __threadfence();
        s_last = (atomicAdd(&g_done, 1) == NBLK - 1) ? 1 : 0;
    }
    __syncthreads();
    if (!s_last) return;

    // keep = [0..3] ++ heavy(sorted asc, in (4,3687)) ++ [3687..4095]
    {
        int base = 4 * t;
        int rk[4];
        #pragma unroll
        for (int k = 0; k < 4; k++) {
            int c = base + k;
            rk[k] = (c < NCAND) ? __ldcg(&g_rank[c]) : HEAVY;
        }
        int f[4], loc = 0;
        #pragma unroll
        for (int k = 0; k < 4; k++) {
            f[k] = (rk[k] < HEAVY) ? 1 : 0;
            loc += f[k];
        }
        int v = loc;
        #pragma unroll
        for (int o = 1; o < 32; o <<= 1) {
            int n = __shfl_up_sync(0xFFFFFFFFu, v, o);
            if (lane >= o) v += n;
        }
        if (lane == 31) warpsum[w] = v;
        __syncthreads();
        if (w == 0) {
            int s = warpsum[lane];
            #pragma unroll
            for (int o = 1; o < 32; o <<= 1) {
                int n = __shfl_up_sync(0xFFFFFFFFu, s, o);
                if (lane >= o) s += n;
            }
            warpsum[lane] = s;
        }
        __syncthreads();
        int pos = START + v - loc + (w > 0 ? warpsum[w - 1] : 0);
        #pragma unroll
        for (int k = 0; k < 4; k++) {
            if (f[k]) { g_keep[pos] = START + base + k; pos++; }
        }
        if (t < START) g_keep[t] = t;
        if (t < SEQ - RSTART) g_keep[START + HEAVY + t] = RSTART + t;
        if (t == 0) g_done = 0;   // reset for next call
    }
}

// ================= Kernel 3: gather rows (unroll-4, 296x512) ===============
// Kernel boundary guarantees g_keep visibility. Blocks 0-3 also re-zero
// g_sums for the next call (its consumers finished in k_rank).
__global__ void __launch_bounds__(GTHR, 2)
k_gath(const float4* __restrict__ keys,
       const float4* __restrict__ vals,
       float4* __restrict__ out) {
    __shared__ int s_keep[NKEEP];
    const int t = threadIdx.x;
    const int b = blockIdx.x;

    if (b < 4) {
        #pragma unroll
        for (int k = 0; k < 2; k++)
            g_sums[b * 1024 + k * GTHR + t] = 0.0;
    }
    for (int i = t; i < NKEEP; i += GTHR)
        s_keep[i] = g_keep[i];
    __syncthreads();

    const int stride = GBLK * GTHR;           // 151552
    int v = b * GTHR + t;
    for (; v + 3 * stride < TOTAL_G; v += 4 * stride) {
        float4 d[4];
        #pragma unroll
        for (int k = 0; k < 4; k++) {
            int vv  = v + k * stride;
            int d4  = vv & 31;
            int row = vv >> 5;
            int tensor = row / (HEADS * NKEEP);
            int rem = row - tensor * (HEADS * NKEEP);
            int h   = rem / NKEEP;
            int r   = rem - h * NKEEP;
            int s   = s_keep[r];
            const float4* __restrict__ src = tensor ? vals : keys;
            d[k] = __ldcs(&src[(((size_t)h * SEQ + s) << 5) + d4]);
        }
        #pragma unroll
        for (int k = 0; k < 4; k++) out[v + k * stride] = d[k];
    }
    for (; v < TOTAL_G; v += stride) {
        int d4  = v & 31;
        int row = v >> 5;
        int tensor = row / (HEADS * NKEEP);
        int rem = row - tensor * (HEADS * NKEEP);
        int h   = rem / NKEEP;
        int r   = rem - h * NKEEP;
        int s   = s_keep[r];
        const float4* __restrict__ src = tensor ? vals : keys;
        out[v] = __ldcs(&src[(((size_t)h * SEQ + s) << 5) + d4]);
    }
}

extern "C" void kernel_launch(void* const* d_in, const int* in_sizes, int n_in,
                              void* d_out, int out_size) {
    const float* keys = (const float*)d_in[0];   // (1,32,4096,128)
    const float* vals = (const float*)d_in[1];   // (1,32,4096,128)
    const float* attn = (const float*)d_in[2];   // (1,32,1024,4096)
    float* out = (float*)d_out;                  // 2*32*822*128 f32

    k_colsum<<<NBLK, NTHR>>>(attn);
    k_rank<<<NBLK, NTHR>>>();
    k_gath<<<GBLK, GTHR>>>((const float4*)keys, (const float4*)vals,
                           (float4*)out);
}